// round 16
// baseline (speedup 1.0000x reference)
#include <cuda_runtime.h>
#include <cuda_fp16.h>
#include <math.h>
#include <cstring>
#include <cstdint>

#define NDIM 256
#define HDIM 128
#define NIMG 384
#define TOTELEM (NIMG * NDIM * NDIM)
#define EPS 1e-13f

// ---------------------------------------------------------------------------
// Static device memory. Split fp16 bases stored per 32-wide K chunk:
//   [r][chunk][hi32 | lo32]  -> 256 halves per row.
// ---------------------------------------------------------------------------
__device__ float g_Yt[TOTELEM];            // pass1 out, transposed per image
__device__ __half g_beS[HDIM * 256];       // even half-basis, split fp16
__device__ __half g_boS[HDIM * 256];       // odd  half-basis, split fp16

// ---------------------------------------------------------------------------
// Helpers
// ---------------------------------------------------------------------------
__device__ __forceinline__ uint32_t smem_u32(const void* p) {
    uint32_t a;
    asm("{ .reg .u64 t; cvta.to.shared.u64 t, %1; cvt.u32.u64 %0, t; }" : "=r"(a) : "l"(p));
    return a;
}
__device__ __forceinline__ uint32_t h2_u32(__half2 h) {
    uint32_t u;
    memcpy(&u, &h, 4);
    return u;
}
// mma.sync m16n8k16 fp16 -> fp32: D += A*B (in-place)
__device__ __forceinline__ void mma16(float* d, const uint32_t* a, const uint32_t* b) {
    asm volatile(
        "mma.sync.aligned.m16n8k16.row.col.f32.f16.f16.f32 "
        "{%0,%1,%2,%3}, {%4,%5,%6,%7}, {%8,%9}, {%0,%1,%2,%3};"
        : "+f"(d[0]), "+f"(d[1]), "+f"(d[2]), "+f"(d[3])
        : "r"(a[0]), "r"(a[1]), "r"(a[2]), "r"(a[3]), "r"(b[0]), "r"(b[1]));
}
#define CP16(dst, src) asm volatile("cp.async.cg.shared.global [%0], [%1], 16;" :: "r"(dst), "l"(src))
#define CP_COMMIT()    asm volatile("cp.async.commit_group;" ::: "memory")
#define CP_WAIT0()     asm volatile("cp.async.wait_group 0;" ::: "memory")

__device__ __forceinline__ void stcs2(float* p, float2 v) {
    asm volatile("st.global.cs.v2.f32 [%0], {%1, %2};" :: "l"(p), "f"(v.x), "f"(v.y) : "memory");
}

// ---------------------------------------------------------------------------
// Half-basis generation + fp16 split into chunked [hi32|lo32] layout.
//   Ce[r][j] = s_{2r}  * cos(pi*(2j+1)*r/256)
//   Co[r][j] = sqrt(2/256) * cos(pi*(2j+1)*(2r+1)/512)
// ---------------------------------------------------------------------------
__global__ void gen_basis_kernel() {
    int idx = blockIdx.x * blockDim.x + threadIdx.x;   // 0..32767
    int r = (idx >> 7) & 127, j = idx & 127;
    float v;
    if (idx < 16384) {
        float s = (r == 0) ? 0.0625f : 0.08838834764831845f;
        v = s * cospif((float)((2 * j + 1) * r) * (1.0f / 256.0f));
    } else {
        v = 0.08838834764831845f *
            cospif((float)((2 * j + 1) * (2 * r + 1)) * (1.0f / 512.0f));
    }
    __half hi = __float2half_rn(v);
    __half lo = __float2half_rn(v - __half2float(hi));
    __half* dst = (idx < 16384) ? g_beS : g_boS;
    int chunk = j >> 5, pos = j & 31;
    dst[r * 256 + chunk * 64 + pos]      = hi;
    dst[r * 256 + chunk * 64 + 32 + pos] = lo;
}

// ---------------------------------------------------------------------------
// SMEM (in 4-byte words): row of a 32-wide K chunk = [hi32 f16 | lo32 f16 | pad]
// = 36 words (144 B). 36 mod 32 = 4 -> fragment LDS conflict-free.
// Stage = A(128x36) + B(128x36) = 9216 words; double-buffered = 73728 B.
// ---------------------------------------------------------------------------
#define PADW  36
#define BOFFW (128 * PADW)       // 4608 words
#define STAGEW (2 * 128 * PADW)  // 9216 words
#define SMEM_BYTES (2 * STAGEW * 4)
#define NCHUNK 4                 // K = 128 in chunks of 32

// ---------------------------------------------------------------------------
// One 32-wide K chunk: warp tile 64x32, 2 k16 steps, pure LDS + MMA.
// ---------------------------------------------------------------------------
__device__ __forceinline__ void compute_chunk(const uint32_t* __restrict__ buf,
                                              float acc[4][4][4],
                                              int wm, int wn, int grp, int qd) {
    const uint32_t* __restrict__ A = buf;
    const uint32_t* __restrict__ B = buf + BOFFW;
    #pragma unroll
    for (int s = 0; s < 2; s++) {
        const int base = s * 8 + qd;
        uint32_t bh[4][2], bl[4][2];
        #pragma unroll
        for (int nt = 0; nt < 4; nt++) {
            int n = wn * 32 + nt * 8 + grp;
            bh[nt][0] = B[n * PADW + base];
            bh[nt][1] = B[n * PADW + base + 4];
            bl[nt][0] = B[n * PADW + 16 + base];
            bl[nt][1] = B[n * PADW + 16 + base + 4];
        }
        #pragma unroll
        for (int mt = 0; mt < 4; mt++) {
            int r = wm * 64 + mt * 16 + grp;
            uint32_t ah[4] = { A[r * PADW + base],      A[(r + 8) * PADW + base],
                               A[r * PADW + base + 4],  A[(r + 8) * PADW + base + 4] };
            uint32_t al[4] = { A[r * PADW + 16 + base],     A[(r + 8) * PADW + 16 + base],
                               A[r * PADW + 16 + base + 4], A[(r + 8) * PADW + 16 + base + 4] };
            #pragma unroll
            for (int nt = 0; nt < 4; nt++) mma16(acc[mt][nt], ah, bh[nt]);
            #pragma unroll
            for (int nt = 0; nt < 4; nt++) mma16(acc[mt][nt], ah, bl[nt]);
            #pragma unroll
            for (int nt = 0; nt < 4; nt++) mma16(acc[mt][nt], al, bh[nt]);
        }
    }
}

// Fold prefetch: thread handles 8 consecutive k per row, 2 rows.
// f[it][e] = src[r][j0+e] + sgn*src[r][255-j0-e], j0 = c*32 + q*8.
__device__ __forceinline__ void ldg_fold(float f[2][8], const float* __restrict__ src,
                                         int c, int tid, float sgn) {
    const int q = tid & 3;
    const int j0 = c * 32 + q * 8;
    #pragma unroll
    for (int it = 0; it < 2; it++) {
        int r = (tid >> 2) + it * 64;
        const float* row = src + (size_t)r * NDIM;
        float4 a0 = *(const float4*)(row + j0);
        float4 a1 = *(const float4*)(row + j0 + 4);
        float4 m0 = *(const float4*)(row + 252 - j0);
        float4 m1 = *(const float4*)(row + 248 - j0);
        f[it][0] = fmaf(sgn, m0.w, a0.x);
        f[it][1] = fmaf(sgn, m0.z, a0.y);
        f[it][2] = fmaf(sgn, m0.y, a0.z);
        f[it][3] = fmaf(sgn, m0.x, a0.w);
        f[it][4] = fmaf(sgn, m1.w, a1.x);
        f[it][5] = fmaf(sgn, m1.z, a1.y);
        f[it][6] = fmaf(sgn, m1.y, a1.z);
        f[it][7] = fmaf(sgn, m1.x, a1.w);
    }
}
// Split once to fp16 hi/lo and store 16B each.
__device__ __forceinline__ void sts_fold(float* __restrict__ smemf, int wordBase,
                                         const float f[2][8], int tid) {
    const int q = tid & 3;
    #pragma unroll
    for (int it = 0; it < 2; it++) {
        int r = (tid >> 2) + it * 64;
        __half h[8];
        float l[8];
        #pragma unroll
        for (int e = 0; e < 8; e++) {
            h[e] = __float2half_rn(f[it][e]);
            l[e] = f[it][e] - __half2float(h[e]);
        }
        uint4 hv, lv;
        hv.x = h2_u32(__halves2half2(h[0], h[1]));
        hv.y = h2_u32(__halves2half2(h[2], h[3]));
        hv.z = h2_u32(__halves2half2(h[4], h[5]));
        hv.w = h2_u32(__halves2half2(h[6], h[7]));
        lv.x = h2_u32(__floats2half2_rn(l[0], l[1]));
        lv.y = h2_u32(__floats2half2_rn(l[2], l[3]));
        lv.z = h2_u32(__floats2half2_rn(l[4], l[5]));
        lv.w = h2_u32(__floats2half2_rn(l[6], l[7]));
        *(uint4*)(smemf + wordBase + r * PADW + q * 4)      = hv;
        *(uint4*)(smemf + wordBase + r * PADW + 16 + q * 4) = lv;
    }
}
// Split-basis staging via cp.async: 128B (hi32|lo32) per row per chunk.
__device__ __forceinline__ void stage_basis(uint32_t sb, int buf, int regionOff,
                                            const __half* __restrict__ Bmat,
                                            int c, int tid) {
    const int r0 = tid >> 3, q8 = tid & 7;
    #pragma unroll
    for (int it = 0; it < 4; it++) {
        int r = r0 + it * 32;
        CP16(sb + (buf * STAGEW + regionOff + r * PADW + q8 * 4) * 4,
             Bmat + (size_t)r * 256 + c * 64 + q8 * 8);
    }
}

// ---------------------------------------------------------------------------
// Pass 1: Y[m, 2r+par] = sum_{j<128} fold_par(X)[m, j] * Cpar[r, j].
// ---------------------------------------------------------------------------
__global__ void __launch_bounds__(256, 2) dct_p1(const float* __restrict__ X) {
    extern __shared__ float smem[];
    const uint32_t sb = smem_u32(smem);
    const int tid = threadIdx.x, lane = tid & 31, wid = tid >> 5;
    const int wm = wid >> 2, wn = wid & 3, grp = lane >> 2, qd = lane & 3;
    const int par = blockIdx.x & 1;
    const int tile = blockIdx.x >> 1;
    const int img = tile >> 1, i0 = (tile & 1) * 128;
    const float* Arow = X + (size_t)(img * NDIM + i0) * NDIM;
    const __half* Bmat = par ? g_boS : g_beS;
    const float sgn = par ? -1.0f : 1.0f;

    float acc[4][4][4] = {};
    float fold[2][8];

    ldg_fold(fold, Arow, 0, tid, sgn);
    stage_basis(sb, 0, BOFFW, Bmat, 0, tid);
    CP_COMMIT();

    for (int c = 0; c < NCHUNK; c++) {
        CP_WAIT0();
        __syncthreads();
        sts_fold(smem, (c & 1) * STAGEW, fold, tid);
        if (c < NCHUNK - 1) {
            ldg_fold(fold, Arow, c + 1, tid, sgn);
            stage_basis(sb, (c + 1) & 1, BOFFW, Bmat, c + 1, tid);
            CP_COMMIT();
        }
        __syncthreads();
        compute_chunk((const uint32_t*)smem + (c & 1) * STAGEW, acc, wm, wn, grp, qd);
    }
    __syncthreads();

    // Transpose through SMEM (stride 132, conflict-free), coalesced store.
    float* T = smem;
    #pragma unroll
    for (int mt = 0; mt < 4; mt++)
        #pragma unroll
        for (int nt = 0; nt < 4; nt++) {
            int m = wm * 64 + mt * 16 + grp;
            int n = wn * 32 + nt * 8 + 2 * qd;
            T[(size_t)n * 132 + m]           = acc[mt][nt][0];
            T[(size_t)(n + 1) * 132 + m]     = acc[mt][nt][1];
            T[(size_t)n * 132 + m + 8]       = acc[mt][nt][2];
            T[(size_t)(n + 1) * 132 + m + 8] = acc[mt][nt][3];
        }
    __syncthreads();

    float* dst = g_Yt + (size_t)img * NDIM * NDIM;
    #pragma unroll
    for (int rr = 0; rr < 16; rr++) {
        int n = wid * 16 + rr;
        float4 v = *(float4*)&T[(size_t)n * 132 + lane * 4];
        *(float4*)(dst + (size_t)(2 * n + par) * NDIM + i0 + lane * 4) = v;
    }
}

// ---------------------------------------------------------------------------
// Pass 2: out[img, 2r+par, k2] = f( sum_{j<128} Cpar[r, j] * fold_par(Yt)[k2, j] ).
// ---------------------------------------------------------------------------
__global__ void __launch_bounds__(256, 2) dct_p2(float* __restrict__ Out,
                                                 const float* __restrict__ meanp,
                                                 const float* __restrict__ stdp) {
    extern __shared__ float smem[];
    const uint32_t sb = smem_u32(smem);
    const int tid = threadIdx.x, lane = tid & 31, wid = tid >> 5;
    const int wm = wid >> 2, wn = wid & 3, grp = lane >> 2, qd = lane & 3;
    const int par = blockIdx.x & 1;
    const int n0 = (blockIdx.x >> 1) * 128;    // k2 tile
    const int img = NIMG - 1 - blockIdx.y;     // newest-first
    const float* Brow = g_Yt + (size_t)img * NDIM * NDIM + (size_t)n0 * NDIM;
    const __half* Amat = par ? g_boS : g_beS;
    const float sgn = par ? -1.0f : 1.0f;

    float acc[4][4][4] = {};
    float fold[2][8];

    ldg_fold(fold, Brow, 0, tid, sgn);
    stage_basis(sb, 0, 0, Amat, 0, tid);
    CP_COMMIT();

    for (int c = 0; c < NCHUNK; c++) {
        CP_WAIT0();
        __syncthreads();
        sts_fold(smem, (c & 1) * STAGEW + BOFFW, fold, tid);
        if (c < NCHUNK - 1) {
            ldg_fold(fold, Brow, c + 1, tid, sgn);
            stage_basis(sb, (c + 1) & 1, 0, Amat, c + 1, tid);
            CP_COMMIT();
        }
        __syncthreads();
        compute_chunk((const uint32_t*)smem + (c & 1) * STAGEW, acc, wm, wn, grp, qd);
    }

    const float mean = *meanp;
    const float istd = 1.0f / (*stdp);
    const float sa = 0.69314718055994531f * istd;   // ln2 * istd
    const float sbias = -mean * istd;
    float* o = Out + (size_t)img * NDIM * NDIM;
    #pragma unroll
    for (int mt = 0; mt < 4; mt++)
        #pragma unroll
        for (int nt = 0; nt < 4; nt++) {
            int m = wm * 64 + mt * 16 + grp;                 // local half-row
            int n = n0 + wn * 32 + nt * 8 + 2 * qd;
            float2 v;
            v.x = fmaf(__log2f(fabsf(acc[mt][nt][0]) + EPS), sa, sbias);
            v.y = fmaf(__log2f(fabsf(acc[mt][nt][1]) + EPS), sa, sbias);
            stcs2(o + (size_t)(2 * m + par) * NDIM + n, v);
            v.x = fmaf(__log2f(fabsf(acc[mt][nt][2]) + EPS), sa, sbias);
            v.y = fmaf(__log2f(fabsf(acc[mt][nt][3]) + EPS), sa, sbias);
            stcs2(o + (size_t)(2 * (m + 8) + par) * NDIM + n, v);
        }
}

// ---------------------------------------------------------------------------
extern "C" void kernel_launch(void* const* d_in, const int* in_sizes, int n_in,
                              void* d_out, int out_size) {
    (void)in_sizes; (void)n_in; (void)out_size;
    const float* x     = (const float*)d_in[0];
    const float* meanp = (const float*)d_in[1];
    const float* stdp  = (const float*)d_in[2];
    float* out = (float*)d_out;

    cudaFuncSetAttribute(dct_p1, cudaFuncAttributeMaxDynamicSharedMemorySize, SMEM_BYTES);
    cudaFuncSetAttribute(dct_p2, cudaFuncAttributeMaxDynamicSharedMemorySize, SMEM_BYTES);

    gen_basis_kernel<<<128, 256>>>();
    dct_p1<<<dim3(1536), 256, SMEM_BYTES>>>(x);
    dct_p2<<<dim3(4, NIMG), 256, SMEM_BYTES>>>(out, meanp, stdp);
}

// round 17
// speedup vs baseline: 1.0083x; 1.0083x over previous
#include <cuda_runtime.h>
#include <cuda_fp16.h>
#include <math.h>
#include <cstring>
#include <cstdint>

#define NDIM 256
#define HDIM 128
#define NIMG 384
#define TOTELEM (NIMG * NDIM * NDIM)
#define EPS 1e-13f

// ---------------------------------------------------------------------------
// Static device memory. Split fp16 bases stored per 32-wide K chunk:
//   [r][chunk][hi32 | lo32]  -> 256 halves per row.
// ---------------------------------------------------------------------------
__device__ float g_Yt[TOTELEM];            // pass1 out, transposed per image
__device__ __half g_beS[HDIM * 256];       // even half-basis, split fp16
__device__ __half g_boS[HDIM * 256];       // odd  half-basis, split fp16

// ---------------------------------------------------------------------------
// Helpers
// ---------------------------------------------------------------------------
__device__ __forceinline__ uint32_t smem_u32(const void* p) {
    uint32_t a;
    asm("{ .reg .u64 t; cvta.to.shared.u64 t, %1; cvt.u32.u64 %0, t; }" : "=r"(a) : "l"(p));
    return a;
}
__device__ __forceinline__ uint32_t h2_u32(__half2 h) {
    uint32_t u;
    memcpy(&u, &h, 4);
    return u;
}
// mma.sync m16n8k16 fp16 -> fp32: D += A*B (in-place)
__device__ __forceinline__ void mma16(float* d, const uint32_t* a, const uint32_t* b) {
    asm volatile(
        "mma.sync.aligned.m16n8k16.row.col.f32.f16.f16.f32 "
        "{%0,%1,%2,%3}, {%4,%5,%6,%7}, {%8,%9}, {%0,%1,%2,%3};"
        : "+f"(d[0]), "+f"(d[1]), "+f"(d[2]), "+f"(d[3])
        : "r"(a[0]), "r"(a[1]), "r"(a[2]), "r"(a[3]), "r"(b[0]), "r"(b[1]));
}
#define CP16(dst, src) asm volatile("cp.async.cg.shared.global [%0], [%1], 16;" :: "r"(dst), "l"(src))
#define CP_COMMIT()    asm volatile("cp.async.commit_group;" ::: "memory")
#define CP_WAIT0()     asm volatile("cp.async.wait_group 0;" ::: "memory")

__device__ __forceinline__ void stcs2(float* p, float2 v) {
    asm volatile("st.global.cs.v2.f32 [%0], {%1, %2};" :: "l"(p), "f"(v.x), "f"(v.y) : "memory");
}

// ---------------------------------------------------------------------------
// Half-basis generation + fp16 split into chunked [hi32|lo32] layout.
//   Ce[r][j] = s_{2r}  * cos(pi*(2j+1)*r/256)
//   Co[r][j] = sqrt(2/256) * cos(pi*(2j+1)*(2r+1)/512)
// ---------------------------------------------------------------------------
__global__ void gen_basis_kernel() {
    int idx = blockIdx.x * blockDim.x + threadIdx.x;   // 0..32767
    int r = (idx >> 7) & 127, j = idx & 127;
    float v;
    if (idx < 16384) {
        float s = (r == 0) ? 0.0625f : 0.08838834764831845f;
        v = s * cospif((float)((2 * j + 1) * r) * (1.0f / 256.0f));
    } else {
        v = 0.08838834764831845f *
            cospif((float)((2 * j + 1) * (2 * r + 1)) * (1.0f / 512.0f));
    }
    __half hi = __float2half_rn(v);
    __half lo = __float2half_rn(v - __half2float(hi));
    __half* dst = (idx < 16384) ? g_beS : g_boS;
    int chunk = j >> 5, pos = j & 31;
    dst[r * 256 + chunk * 64 + pos]      = hi;
    dst[r * 256 + chunk * 64 + 32 + pos] = lo;
}

// ---------------------------------------------------------------------------
// SMEM (in 4-byte words): row of a 32-wide K chunk = [hi32 f16 | lo32 f16 | pad]
// = 36 words (144 B). 36 mod 32 = 4 -> fragment LDS conflict-free.
// Stage = A(128x36) + B(128x36) = 9216 words; double-buffered = 73728 B.
// ---------------------------------------------------------------------------
#define PADW  36
#define BOFFW (128 * PADW)       // 4608 words
#define STAGEW (2 * 128 * PADW)  // 9216 words
#define SMEM_BYTES (2 * STAGEW * 4)
#define NCHUNK 4                 // K = 128 in chunks of 32

// ---------------------------------------------------------------------------
// One 32-wide K chunk: warp tile 64x32, 2 k16 steps, pure LDS + MMA.
// ---------------------------------------------------------------------------
__device__ __forceinline__ void compute_chunk(const uint32_t* __restrict__ buf,
                                              float acc[4][4][4],
                                              int wm, int wn, int grp, int qd) {
    const uint32_t* __restrict__ A = buf;
    const uint32_t* __restrict__ B = buf + BOFFW;
    #pragma unroll
    for (int s = 0; s < 2; s++) {
        const int base = s * 8 + qd;
        uint32_t bh[4][2], bl[4][2];
        #pragma unroll
        for (int nt = 0; nt < 4; nt++) {
            int n = wn * 32 + nt * 8 + grp;
            bh[nt][0] = B[n * PADW + base];
            bh[nt][1] = B[n * PADW + base + 4];
            bl[nt][0] = B[n * PADW + 16 + base];
            bl[nt][1] = B[n * PADW + 16 + base + 4];
        }
        #pragma unroll
        for (int mt = 0; mt < 4; mt++) {
            int r = wm * 64 + mt * 16 + grp;
            uint32_t ah[4] = { A[r * PADW + base],      A[(r + 8) * PADW + base],
                               A[r * PADW + base + 4],  A[(r + 8) * PADW + base + 4] };
            uint32_t al[4] = { A[r * PADW + 16 + base],     A[(r + 8) * PADW + 16 + base],
                               A[r * PADW + 16 + base + 4], A[(r + 8) * PADW + 16 + base + 4] };
            #pragma unroll
            for (int nt = 0; nt < 4; nt++) mma16(acc[mt][nt], ah, bh[nt]);
            #pragma unroll
            for (int nt = 0; nt < 4; nt++) mma16(acc[mt][nt], ah, bl[nt]);
            #pragma unroll
            for (int nt = 0; nt < 4; nt++) mma16(acc[mt][nt], al, bh[nt]);
        }
    }
}

// Fold prefetch: thread handles 8 consecutive k per row, 2 rows.
// f[it][e] = src[r][j0+e] + sgn*src[r][255-j0-e], j0 = c*32 + q*8.
__device__ __forceinline__ void ldg_fold(float f[2][8], const float* __restrict__ src,
                                         int c, int tid, float sgn) {
    const int q = tid & 3;
    const int j0 = c * 32 + q * 8;
    #pragma unroll
    for (int it = 0; it < 2; it++) {
        int r = (tid >> 2) + it * 64;
        const float* row = src + (size_t)r * NDIM;
        float4 a0 = *(const float4*)(row + j0);
        float4 a1 = *(const float4*)(row + j0 + 4);
        float4 m0 = *(const float4*)(row + 252 - j0);
        float4 m1 = *(const float4*)(row + 248 - j0);
        f[it][0] = fmaf(sgn, m0.w, a0.x);
        f[it][1] = fmaf(sgn, m0.z, a0.y);
        f[it][2] = fmaf(sgn, m0.y, a0.z);
        f[it][3] = fmaf(sgn, m0.x, a0.w);
        f[it][4] = fmaf(sgn, m1.w, a1.x);
        f[it][5] = fmaf(sgn, m1.z, a1.y);
        f[it][6] = fmaf(sgn, m1.y, a1.z);
        f[it][7] = fmaf(sgn, m1.x, a1.w);
    }
}
// Split once to fp16 hi/lo and store 16B each.
__device__ __forceinline__ void sts_fold(float* __restrict__ smemf, int wordBase,
                                         const float f[2][8], int tid) {
    const int q = tid & 3;
    #pragma unroll
    for (int it = 0; it < 2; it++) {
        int r = (tid >> 2) + it * 64;
        __half h[8];
        float l[8];
        #pragma unroll
        for (int e = 0; e < 8; e++) {
            h[e] = __float2half_rn(f[it][e]);
            l[e] = f[it][e] - __half2float(h[e]);
        }
        uint4 hv, lv;
        hv.x = h2_u32(__halves2half2(h[0], h[1]));
        hv.y = h2_u32(__halves2half2(h[2], h[3]));
        hv.z = h2_u32(__halves2half2(h[4], h[5]));
        hv.w = h2_u32(__halves2half2(h[6], h[7]));
        lv.x = h2_u32(__floats2half2_rn(l[0], l[1]));
        lv.y = h2_u32(__floats2half2_rn(l[2], l[3]));
        lv.z = h2_u32(__floats2half2_rn(l[4], l[5]));
        lv.w = h2_u32(__floats2half2_rn(l[6], l[7]));
        *(uint4*)(smemf + wordBase + r * PADW + q * 4)      = hv;
        *(uint4*)(smemf + wordBase + r * PADW + 16 + q * 4) = lv;
    }
}
// Split-basis staging via cp.async: 128B (hi32|lo32) per row per chunk.
__device__ __forceinline__ void stage_basis(uint32_t sb, int buf, int regionOff,
                                            const __half* __restrict__ Bmat,
                                            int c, int tid) {
    const int r0 = tid >> 3, q8 = tid & 7;
    #pragma unroll
    for (int it = 0; it < 4; it++) {
        int r = r0 + it * 32;
        CP16(sb + (buf * STAGEW + regionOff + r * PADW + q8 * 4) * 4,
             Bmat + (size_t)r * 256 + c * 64 + q8 * 8);
    }
}

// ---------------------------------------------------------------------------
// Pass 1: Y[m, 2r+par] = sum_{j<128} fold_par(X)[m, j] * Cpar[r, j].
// ---------------------------------------------------------------------------
__global__ void __launch_bounds__(256, 2) dct_p1(const float* __restrict__ X) {
    extern __shared__ float smem[];
    const uint32_t sb = smem_u32(smem);
    const int tid = threadIdx.x, lane = tid & 31, wid = tid >> 5;
    const int wm = wid >> 2, wn = wid & 3, grp = lane >> 2, qd = lane & 3;
    const int par = blockIdx.x & 1;
    const int tile = blockIdx.x >> 1;
    const int img = tile >> 1, i0 = (tile & 1) * 128;
    const float* Arow = X + (size_t)(img * NDIM + i0) * NDIM;
    const __half* Bmat = par ? g_boS : g_beS;
    const float sgn = par ? -1.0f : 1.0f;

    float acc[4][4][4] = {};
    float fold[2][8];

    ldg_fold(fold, Arow, 0, tid, sgn);
    stage_basis(sb, 0, BOFFW, Bmat, 0, tid);
    CP_COMMIT();

    for (int c = 0; c < NCHUNK; c++) {
        CP_WAIT0();
        __syncthreads();
        sts_fold(smem, (c & 1) * STAGEW, fold, tid);
        if (c < NCHUNK - 1) {
            ldg_fold(fold, Arow, c + 1, tid, sgn);
            stage_basis(sb, (c + 1) & 1, BOFFW, Bmat, c + 1, tid);
            CP_COMMIT();
        }
        __syncthreads();
        compute_chunk((const uint32_t*)smem + (c & 1) * STAGEW, acc, wm, wn, grp, qd);
    }
    __syncthreads();

    // Transpose through SMEM (stride 132, conflict-free), coalesced store.
    float* T = smem;
    #pragma unroll
    for (int mt = 0; mt < 4; mt++)
        #pragma unroll
        for (int nt = 0; nt < 4; nt++) {
            int m = wm * 64 + mt * 16 + grp;
            int n = wn * 32 + nt * 8 + 2 * qd;
            T[(size_t)n * 132 + m]           = acc[mt][nt][0];
            T[(size_t)(n + 1) * 132 + m]     = acc[mt][nt][1];
            T[(size_t)n * 132 + m + 8]       = acc[mt][nt][2];
            T[(size_t)(n + 1) * 132 + m + 8] = acc[mt][nt][3];
        }
    __syncthreads();

    float* dst = g_Yt + (size_t)img * NDIM * NDIM;
    #pragma unroll
    for (int rr = 0; rr < 16; rr++) {
        int n = wid * 16 + rr;
        float4 v = *(float4*)&T[(size_t)n * 132 + lane * 4];
        *(float4*)(dst + (size_t)(2 * n + par) * NDIM + i0 + lane * 4) = v;
    }
}

// ---------------------------------------------------------------------------
// Pass 2: out[img, 2r+par, k2] = f( sum_{j<128} Cpar[r, j] * fold_par(Yt)[k2, j] ).
// ---------------------------------------------------------------------------
__global__ void __launch_bounds__(256, 2) dct_p2(float* __restrict__ Out,
                                                 const float* __restrict__ meanp,
                                                 const float* __restrict__ stdp) {
    extern __shared__ float smem[];
    const uint32_t sb = smem_u32(smem);
    const int tid = threadIdx.x, lane = tid & 31, wid = tid >> 5;
    const int wm = wid >> 2, wn = wid & 3, grp = lane >> 2, qd = lane & 3;
    const int par = blockIdx.x & 1;
    const int n0 = (blockIdx.x >> 1) * 128;    // k2 tile
    const int img = NIMG - 1 - blockIdx.y;     // newest-first
    const float* Brow = g_Yt + (size_t)img * NDIM * NDIM + (size_t)n0 * NDIM;
    const __half* Amat = par ? g_boS : g_beS;
    const float sgn = par ? -1.0f : 1.0f;

    float acc[4][4][4] = {};
    float fold[2][8];

    ldg_fold(fold, Brow, 0, tid, sgn);
    stage_basis(sb, 0, 0, Amat, 0, tid);
    CP_COMMIT();

    for (int c = 0; c < NCHUNK; c++) {
        CP_WAIT0();
        __syncthreads();
        sts_fold(smem, (c & 1) * STAGEW + BOFFW, fold, tid);
        if (c < NCHUNK - 1) {
            ldg_fold(fold, Brow, c + 1, tid, sgn);
            stage_basis(sb, (c + 1) & 1, 0, Amat, c + 1, tid);
            CP_COMMIT();
        }
        __syncthreads();
        compute_chunk((const uint32_t*)smem + (c & 1) * STAGEW, acc, wm, wn, grp, qd);
    }

    const float mean = *meanp;
    const float istd = 1.0f / (*stdp);
    const float sa = 0.69314718055994531f * istd;   // ln2 * istd
    const float sbias = -mean * istd;
    float* o = Out + (size_t)img * NDIM * NDIM;
    #pragma unroll
    for (int mt = 0; mt < 4; mt++)
        #pragma unroll
        for (int nt = 0; nt < 4; nt++) {
            int m = wm * 64 + mt * 16 + grp;                 // local half-row
            int n = n0 + wn * 32 + nt * 8 + 2 * qd;
            float2 v;
            v.x = fmaf(__log2f(fabsf(acc[mt][nt][0]) + EPS), sa, sbias);
            v.y = fmaf(__log2f(fabsf(acc[mt][nt][1]) + EPS), sa, sbias);
            stcs2(o + (size_t)(2 * m + par) * NDIM + n, v);
            v.x = fmaf(__log2f(fabsf(acc[mt][nt][2]) + EPS), sa, sbias);
            v.y = fmaf(__log2f(fabsf(acc[mt][nt][3]) + EPS), sa, sbias);
            stcs2(o + (size_t)(2 * (m + 8) + par) * NDIM + n, v);
        }
}

// ---------------------------------------------------------------------------
extern "C" void kernel_launch(void* const* d_in, const int* in_sizes, int n_in,
                              void* d_out, int out_size) {
    (void)in_sizes; (void)n_in; (void)out_size;
    const float* x     = (const float*)d_in[0];
    const float* meanp = (const float*)d_in[1];
    const float* stdp  = (const float*)d_in[2];
    float* out = (float*)d_out;

    cudaFuncSetAttribute(dct_p1, cudaFuncAttributeMaxDynamicSharedMemorySize, SMEM_BYTES);
    cudaFuncSetAttribute(dct_p2, cudaFuncAttributeMaxDynamicSharedMemorySize, SMEM_BYTES);

    gen_basis_kernel<<<128, 256>>>();
    dct_p1<<<dim3(1536), 256, SMEM_BYTES>>>(x);
    dct_p2<<<dim3(4, NIMG), 256, SMEM_BYTES>>>(out, meanp, stdp);
}